// round 4
// baseline (speedup 1.0000x reference)
#include <cuda_runtime.h>
#include <math.h>

#define TT   2048
#define HID  2048
#define NH   16
#define NKV  8
#define HD   128
#define QKVN 4096   /* NH*HD + 2*NKV*HD */

// ---------------- scratch (device globals: alloc-free rule) ----------------
__device__ float g_qkv[(size_t)TT * QKVN];      // 32 MB
__device__ float g_q  [(size_t)TT * NH * HD];   // 16 MB  (normed+roped Q)
__device__ float g_k  [(size_t)TT * NKV * HD];  //  8 MB  (normed+roped K)
__device__ float g_att[(size_t)TT * NH * HD];   // 16 MB  (attention output)

// ======================================================================
// GEMM: C[M,N] = A[M,K] * B[N,K]^T   (both row-major, K contiguous)
// 128x128 block tile, K-step 16, 256 threads, 8x8 microtile.
// Double-buffered smem: one __syncthreads per K-step.
// ======================================================================
__global__ __launch_bounds__(256) void gemm_nt(
    const float* __restrict__ A, const float* __restrict__ B,
    float* __restrict__ C, int M, int N, int K)
{
    __shared__ float As[2][16][136];   // As[buf][k][m]
    __shared__ float Bs[2][16][136];   // Bs[buf][k][n]

    const int tid = threadIdx.x;
    const int bm  = blockIdx.y * 128;
    const int bn  = blockIdx.x * 128;
    const int tx  = tid & 15;
    const int ty  = tid >> 4;
    const int lrow = tid >> 1;        // 0..127
    const int w0   = (tid & 1) * 8;   // float offset 0 or 8 within the 16-float row

    float acc[8][8];
    #pragma unroll
    for (int i = 0; i < 8; i++)
        #pragma unroll
        for (int j = 0; j < 8; j++) acc[i][j] = 0.f;

    const float* Ap = A + (size_t)(bm + lrow) * K + w0;
    const float* Bp = B + (size_t)(bn + lrow) * K + w0;

    // preload first K-tile into buffer 0
    {
        float4 a0 = *(const float4*)(Ap);
        float4 a1 = *(const float4*)(Ap + 4);
        float4 b0 = *(const float4*)(Bp);
        float4 b1 = *(const float4*)(Bp + 4);
        As[0][w0+0][lrow] = a0.x; As[0][w0+1][lrow] = a0.y;
        As[0][w0+2][lrow] = a0.z; As[0][w0+3][lrow] = a0.w;
        As[0][w0+4][lrow] = a1.x; As[0][w0+5][lrow] = a1.y;
        As[0][w0+6][lrow] = a1.z; As[0][w0+7][lrow] = a1.w;
        Bs[0][w0+0][lrow] = b0.x; Bs[0][w0+1][lrow] = b0.y;
        Bs[0][w0+2][lrow] = b0.z; Bs[0][w0+3][lrow] = b0.w;
        Bs[0][w0+4][lrow] = b1.x; Bs[0][w0+5][lrow] = b1.y;
        Bs[0][w0+6][lrow] = b1.z; Bs[0][w0+7][lrow] = b1.w;
    }
    __syncthreads();

    int cur = 0;
    for (int k0 = 0; k0 < K; k0 += 16) {
        const int nxt = k0 + 16;
        float4 na0, na1, nb0, nb1;
        const bool have_next = (nxt < K);
        if (have_next) {                      // prefetch next tile (overlaps FFMA)
            na0 = *(const float4*)(Ap + nxt);
            na1 = *(const float4*)(Ap + nxt + 4);
            nb0 = *(const float4*)(Bp + nxt);
            nb1 = *(const float4*)(Bp + nxt + 4);
        }

        #pragma unroll
        for (int kk = 0; kk < 16; kk++) {
            float a[8], b[8];
            float4 t;
            t = *(const float4*)&As[cur][kk][ty*8];     a[0]=t.x; a[1]=t.y; a[2]=t.z; a[3]=t.w;
            t = *(const float4*)&As[cur][kk][ty*8 + 4]; a[4]=t.x; a[5]=t.y; a[6]=t.z; a[7]=t.w;
            t = *(const float4*)&Bs[cur][kk][tx*8];     b[0]=t.x; b[1]=t.y; b[2]=t.z; b[3]=t.w;
            t = *(const float4*)&Bs[cur][kk][tx*8 + 4]; b[4]=t.x; b[5]=t.y; b[6]=t.z; b[7]=t.w;
            #pragma unroll
            for (int i = 0; i < 8; i++)
                #pragma unroll
                for (int j = 0; j < 8; j++)
                    acc[i][j] += a[i] * b[j];
        }

        if (have_next) {
            const int nb = cur ^ 1;
            As[nb][w0+0][lrow] = na0.x; As[nb][w0+1][lrow] = na0.y;
            As[nb][w0+2][lrow] = na0.z; As[nb][w0+3][lrow] = na0.w;
            As[nb][w0+4][lrow] = na1.x; As[nb][w0+5][lrow] = na1.y;
            As[nb][w0+6][lrow] = na1.z; As[nb][w0+7][lrow] = na1.w;
            Bs[nb][w0+0][lrow] = nb0.x; Bs[nb][w0+1][lrow] = nb0.y;
            Bs[nb][w0+2][lrow] = nb0.z; Bs[nb][w0+3][lrow] = nb0.w;
            Bs[nb][w0+4][lrow] = nb1.x; Bs[nb][w0+5][lrow] = nb1.y;
            Bs[nb][w0+6][lrow] = nb1.z; Bs[nb][w0+7][lrow] = nb1.w;
            __syncthreads();
            cur = nb;
        }
    }

    #pragma unroll
    for (int i = 0; i < 8; i++) {
        float* Cp = C + (size_t)(bm + ty*8 + i) * N + bn + tx*8;
        float4 c0 = make_float4(acc[i][0], acc[i][1], acc[i][2], acc[i][3]);
        float4 c1 = make_float4(acc[i][4], acc[i][5], acc[i][6], acc[i][7]);
        *(float4*)Cp       = c0;
        *((float4*)Cp + 1) = c1;
    }
}

// ======================================================================
// RMSNorm + RoPE, warp-local: one warp per (t, head-slot).
// Lane owns dims {lane, lane+32, lane+64, lane+96}; RoPE pair (i, i+64)
// is entirely lane-local -> no shared memory, no block syncs.
// ======================================================================
__global__ __launch_bounds__(128) void norm_rope(
    const int* __restrict__ positions,
    const float* __restrict__ qw, const float* __restrict__ kw)
{
    const int slot = blockIdx.x * 4 + (threadIdx.x >> 5); // 0..TT*(NH+NKV)-1
    const int lane = threadIdx.x & 31;
    const int t  = slot / (NH + NKV);
    const int hh = slot % (NH + NKV);
    const bool isq = hh < NH;

    const float* x = g_qkv + (size_t)t * QKVN +
                     (isq ? hh * HD : NH * HD + (hh - NH) * HD);

    float v0 = x[lane];
    float v1 = x[lane + 32];
    float v2 = x[lane + 64];
    float v3 = x[lane + 96];

    float ss = v0*v0 + v1*v1 + v2*v2 + v3*v3;
    #pragma unroll
    for (int o = 16; o; o >>= 1) ss += __shfl_xor_sync(0xffffffffu, ss, o);

    float r = rsqrtf(ss * (1.0f / HD) + 1e-6f);
    const float* w = isq ? qw : kw;
    float x0 = v0 * r * w[lane];
    float x1 = v1 * r * w[lane + 32];
    float x2 = v2 * r * w[lane + 64];
    float x3 = v3 * r * w[lane + 96];

    const float pos = (float)positions[t];
    float f0 = 1.0f / powf(1000000.0f, (float)lane        * (1.0f / 64.0f));
    float f1 = 1.0f / powf(1000000.0f, (float)(lane + 32) * (1.0f / 64.0f));
    float s0, c0, s1, c1;
    sincosf(pos * f0, &s0, &c0);
    sincosf(pos * f1, &s1, &c1);

    // pairs: (lane, lane+64) uses f0 ; (lane+32, lane+96) uses f1
    float o0 = x0 * c0 - x2 * s0;   // dim lane        (first half)
    float o1 = x1 * c1 - x3 * s1;   // dim lane+32     (first half)
    float o2 = x2 * c0 + x0 * s0;   // dim lane+64     (second half)
    float o3 = x3 * c1 + x1 * s1;   // dim lane+96     (second half)

    float* dst = isq ? (g_q + (size_t)t * NH * HD + hh * HD)
                     : (g_k + (size_t)t * NKV * HD + (hh - NH) * HD);
    dst[lane]      = o0;
    dst[lane + 32] = o1;
    dst[lane + 64] = o2;
    dst[lane + 96] = o3;
}

// ======================================================================
// Causal GQA flash attention (fp32, online softmax).
// grid: (T/64, NH), 256 threads. 4 threads per query row, each owning an
// interleaved 32-dim chunk: float4 index (d4*4 + lane4) -> conflict-free LDS.
// Dynamic smem: Ks[64][128] + Vs[64][128] = 64 KB.
// ======================================================================
__global__ __launch_bounds__(256) void attn_kernel(float* __restrict__ out)
{
    extern __shared__ float smem_att[];
    float (*Ks)[128] = (float(*)[128])smem_att;
    float (*Vs)[128] = (float(*)[128])(smem_att + 64 * 128);

    const int h     = blockIdx.y;
    const int qb    = (int)(gridDim.x - 1) - (int)blockIdx.x; // heavy blocks first
    const int kvh   = h >> 1;                                  // rep = 2
    const int tid   = threadIdx.x;
    const int row   = tid >> 2;
    const int lane4 = tid & 3;
    const int lane  = tid & 31;
    const int qi    = qb * 64 + row;

    const float scale = 0.08838834764831845f;  // 1/sqrt(128)
    const float NEG   = -1e30f;

    float4 q4[8], o4[8];
    #pragma unroll
    for (int d4 = 0; d4 < 8; d4++) {
        float4 t = *(const float4*)(g_q + (size_t)qi * 2048 + h * 128 + (d4 * 4 + lane4) * 4);
        t.x *= scale; t.y *= scale; t.z *= scale; t.w *= scale;
        q4[d4] = t;
        o4[d4] = make_float4(0.f, 0.f, 0.f, 0.f);
    }
    float m = NEG, l = 0.f;

    for (int kt = 0; kt <= qb; kt++) {
        __syncthreads();
        #pragma unroll
        for (int u = tid; u < 64 * 32; u += 256) {
            int r  = u >> 5;
            int c4 = (u & 31) * 4;
            *(float4*)&Ks[r][c4] =
                *(const float4*)(g_k + ((size_t)(kt * 64 + r) * NKV + kvh) * 128 + c4);
            *(float4*)&Vs[r][c4] =
                *(const float4*)(g_qkv + (size_t)(kt * 64 + r) * QKVN + (NH + NKV) * HD + kvh * 128 + c4);
        }
        __syncthreads();

        float p[16];
        float mt = NEG;
        #pragma unroll
        for (int jj = 0; jj < 16; jj++) {
            float mine = 0.f;
            #pragma unroll
            for (int jofs = 0; jofs < 4; jofs++) {
                int j = jj * 4 + jofs;
                float part = 0.f;
                #pragma unroll
                for (int d4 = 0; d4 < 8; d4++) {
                    float4 kv = *(const float4*)&Ks[j][(d4 * 4 + lane4) * 4];
                    part += q4[d4].x * kv.x + q4[d4].y * kv.y
                          + q4[d4].z * kv.z + q4[d4].w * kv.w;
                }
                part += __shfl_xor_sync(0xffffffffu, part, 1);
                part += __shfl_xor_sync(0xffffffffu, part, 2);
                if (jofs == lane4) mine = part;
            }
            int kj = kt * 64 + jj * 4 + lane4;
            p[jj] = (kj <= qi) ? mine : NEG;
            mt = fmaxf(mt, p[jj]);
        }
        mt = fmaxf(mt, __shfl_xor_sync(0xffffffffu, mt, 1));
        mt = fmaxf(mt, __shfl_xor_sync(0xffffffffu, mt, 2));

        float mnew  = fmaxf(m, mt);
        float alpha = __expf(m - mnew);
        float lt = 0.f;
        #pragma unroll
        for (int jj = 0; jj < 16; jj++) {
            p[jj] = __expf(p[jj] - mnew);
            lt += p[jj];
        }
        lt += __shfl_xor_sync(0xffffffffu, lt, 1);
        lt += __shfl_xor_sync(0xffffffffu, lt, 2);
        l = l * alpha + lt;
        m = mnew;

        #pragma unroll
        for (int d4 = 0; d4 < 8; d4++) {
            o4[d4].x *= alpha; o4[d4].y *= alpha;
            o4[d4].z *= alpha; o4[d4].w *= alpha;
        }

        #pragma unroll
        for (int jj = 0; jj < 16; jj++) {
            #pragma unroll
            for (int jofs = 0; jofs < 4; jofs++) {
                float pj = __shfl_sync(0xffffffffu, p[jj], (lane & ~3) | jofs);
                int j = jj * 4 + jofs;
                #pragma unroll
                for (int d4 = 0; d4 < 8; d4++) {
                    float4 vv = *(const float4*)&Vs[j][(d4 * 4 + lane4) * 4];
                    o4[d4].x += pj * vv.x; o4[d4].y += pj * vv.y;
                    o4[d4].z += pj * vv.z; o4[d4].w += pj * vv.w;
                }
            }
        }
    }

    float invl = 1.f / l;
    #pragma unroll
    for (int d4 = 0; d4 < 8; d4++) {
        float4 t = o4[d4];
        t.x *= invl; t.y *= invl; t.z *= invl; t.w *= invl;
        *(float4*)(out + (size_t)qi * 2048 + h * 128 + (d4 * 4 + lane4) * 4) = t;
    }
}

// ======================================================================
// launch — inputs bound by element count, NOT by position, so any
// metadata ordering (dict / alphabetical) works:
//   qkv_w = 8388608 ; hidden = o_w = 4194304 (hidden first in both
//   orderings) ; positions = 2048 ; q_norm_w = k_norm_w = 128 (identical
//   content, order irrelevant).
// ======================================================================
extern "C" void kernel_launch(void* const* d_in, const int* in_sizes, int n_in,
                              void* d_out, int out_size)
{
    const float* hidden    = 0;
    const int*   positions = 0;
    const float* qkv_w     = 0;
    const float* o_w       = 0;
    const float* qw        = 0;
    const float* kw        = 0;

    for (int i = 0; i < n_in; i++) {
        int s = in_sizes[i];
        if (s == QKVN * HID)            qkv_w = (const float*)d_in[i];
        else if (s == TT * HID) {
            if (!hidden) hidden = (const float*)d_in[i];
            else         o_w    = (const float*)d_in[i];
        }
        else if (s == TT)               positions = (const int*)d_in[i];
        else if (s == HD) {
            if (!qw) qw = (const float*)d_in[i];
            else     kw = (const float*)d_in[i];
        }
    }
    if (!kw) kw = qw;   // safety if only one 128-elem input appears

    float* out = (float*)d_out;

    float *qkv_p, *att_p;
    cudaGetSymbolAddress((void**)&qkv_p, g_qkv);
    cudaGetSymbolAddress((void**)&att_p, g_att);

    cudaFuncSetAttribute(attn_kernel,
                         cudaFuncAttributeMaxDynamicSharedMemorySize, 65536);

    // 1. QKV projection: [T, QKVN] = hidden[T,HID] @ qkv_w[QKVN,HID]^T
    gemm_nt<<<dim3(QKVN / 128, TT / 128), 256>>>(hidden, qkv_w, qkv_p, TT, QKVN, HID);

    // 2. RMSNorm + RoPE on Q and K heads (warp per (t, head))
    norm_rope<<<TT * (NH + NKV) / 4, 128>>>(positions, qw, kw);

    // 3. Causal GQA attention
    attn_kernel<<<dim3(TT / 64, NH), 256, 65536>>>(att_p);

    // 4. Output projection: [T, HID] = att[T, NH*HD] @ o_w[HID, NH*HD]^T
    gemm_nt<<<dim3(HID / 128, TT / 128), 256>>>(att_p, o_w, out, TT, HID, HID);
}

// round 7
// speedup vs baseline: 1.3840x; 1.3840x over previous
#include <cuda_runtime.h>
#include <cuda_bf16.h>
#include <math.h>
#include <stdint.h>

#define TT   2048
#define HID  2048
#define NH   16
#define NKV  8
#define HD   128
#define QKVN 4096   /* NH*HD + 2*NKV*HD */

// ---------------- scratch (device globals: alloc-free rule) ----------------
__device__ float g_qkv[(size_t)TT * QKVN];      // 32 MB
__device__ float g_q  [(size_t)TT * NH * HD];   // 16 MB  (normed+roped Q)
__device__ float g_k  [(size_t)TT * NKV * HD];  //  8 MB  (normed+roped K)
__device__ float g_att[(size_t)TT * NH * HD];   // 16 MB  (attention output)

// bf16 hi/lo split copies for tensor-core GEMMs
__device__ __nv_bfloat16 g_hid_hi[(size_t)TT * HID];
__device__ __nv_bfloat16 g_hid_lo[(size_t)TT * HID];
__device__ __nv_bfloat16 g_w1_hi [(size_t)QKVN * HID];
__device__ __nv_bfloat16 g_w1_lo [(size_t)QKVN * HID];
__device__ __nv_bfloat16 g_ow_hi [(size_t)HID * HID];
__device__ __nv_bfloat16 g_ow_lo [(size_t)HID * HID];
__device__ __nv_bfloat16 g_at_hi [(size_t)TT * HID];
__device__ __nv_bfloat16 g_at_lo [(size_t)TT * HID];

// ======================== helpers ========================
__device__ __forceinline__ uint32_t smem_u32(const void* p) {
    uint32_t a;
    asm("{ .reg .u64 t; cvta.to.shared.u64 t, %1; cvt.u32.u64 %0, t; }"
        : "=r"(a) : "l"(p));
    return a;
}

__device__ __forceinline__ void ldmx4(uint32_t addr, uint32_t& r0, uint32_t& r1,
                                      uint32_t& r2, uint32_t& r3) {
    asm volatile("ldmatrix.sync.aligned.m8n8.x4.shared.b16 {%0,%1,%2,%3}, [%4];"
                 : "=r"(r0), "=r"(r1), "=r"(r2), "=r"(r3) : "r"(addr));
}

__device__ __forceinline__ void mma16816(float* c, const uint32_t* a,
                                         uint32_t b0, uint32_t b1) {
    asm volatile(
        "mma.sync.aligned.m16n8k16.row.col.f32.bf16.bf16.f32 "
        "{%0,%1,%2,%3}, {%4,%5,%6,%7}, {%8,%9}, {%0,%1,%2,%3};"
        : "+f"(c[0]), "+f"(c[1]), "+f"(c[2]), "+f"(c[3])
        : "r"(a[0]), "r"(a[1]), "r"(a[2]), "r"(a[3]), "r"(b0), "r"(b1));
}

// ======================================================================
// fp32 -> bf16 hi/lo split (8 floats per thread)
// ======================================================================
__global__ __launch_bounds__(256) void cvt_hilo(
    const float* __restrict__ x, __nv_bfloat16* __restrict__ hi,
    __nv_bfloat16* __restrict__ lo, int n8)
{
    int i = blockIdx.x * 256 + threadIdx.x;
    if (i >= n8) return;
    float4 a = ((const float4*)x)[i * 2];
    float4 b = ((const float4*)x)[i * 2 + 1];
    float v[8] = {a.x, a.y, a.z, a.w, b.x, b.y, b.z, b.w};
    __nv_bfloat16 h[8], l[8];
    #pragma unroll
    for (int k = 0; k < 8; k++) {
        h[k] = __float2bfloat16(v[k]);
        l[k] = __float2bfloat16(v[k] - __bfloat162float(h[k]));
    }
    *(uint4*)(hi + (size_t)i * 8) = *(uint4*)h;
    *(uint4*)(lo + (size_t)i * 8) = *(uint4*)l;
}

// ======================================================================
// HMMA bf16-split GEMM: C[M,N] = A[M,K] * B[N,K]^T (fp32 via hi/lo,
// D = Ahi*Bhi + Ahi*Blo + Alo*Bhi, fp32 accumulate).
// 128x128 CTA tile, 256 threads (8 warps x 64x32), K-chunk 32,
// double-buffered padded smem (80B rows -> conflict-free ldmatrix).
// ======================================================================
#define KCH    32
#define ROWB   80                        /* 64B data + 16B pad  */
#define MATB   (128 * ROWB)              /* 10240 B per matrix  */
#define BUFB   (4 * MATB)                /* Ahi|Alo|Bhi|Blo     */

__global__ __launch_bounds__(256, 1) void gemm_hmma(
    const __nv_bfloat16* __restrict__ Ahi, const __nv_bfloat16* __restrict__ Alo,
    const __nv_bfloat16* __restrict__ Bhi, const __nv_bfloat16* __restrict__ Blo,
    float* __restrict__ C, int N, int K)
{
    extern __shared__ char smem[];
    const uint32_t sb = smem_u32(smem);
    const int tid  = threadIdx.x;
    const int wid  = tid >> 5;
    const int lane = tid & 31;
    const int bm   = blockIdx.y * 128;
    const int bn   = blockIdx.x * 128;
    const int wm   = wid & 1;            // warp m: 0/1  (64 rows each)
    const int wn   = wid >> 1;           // warp n: 0..3 (32 cols each)

    // fill mapping: row r = tid>>1, 16-elem half ch = (tid&1)*16
    const int r  = tid >> 1;
    const int ch = (tid & 1) * 16;
    const __nv_bfloat16* src[4] = {
        Ahi + (size_t)(bm + r) * K + ch,
        Alo + (size_t)(bm + r) * K + ch,
        Bhi + (size_t)(bn + r) * K + ch,
        Blo + (size_t)(bn + r) * K + ch };
    const uint32_t stoff = (uint32_t)(r * ROWB + ch * 2);

    // ldmatrix per-lane address offsets (within one matrix, one buffer)
    // A tiles (m0-7,k0-7),(m8-15,k0-7),(m0-7,k8-15),(m8-15,k8-15)
    const uint32_t arow = (uint32_t)((lane & 7) + ((lane & 8) ? 8 : 0));
    const uint32_t akb  = (lane & 16) ? 16u : 0u;
    // B tiles (n0-7,k0-7),(n0-7,k8-15),(n8-15,k0-7),(n8-15,k8-15)
    const uint32_t brow = (uint32_t)((lane & 7) + ((lane & 16) ? 8 : 0));
    const uint32_t bkb  = (lane & 8) ? 16u : 0u;

    float acc[4][4][4];
    #pragma unroll
    for (int i = 0; i < 4; i++)
        #pragma unroll
        for (int j = 0; j < 4; j++)
            #pragma unroll
            for (int q = 0; q < 4; q++) acc[i][j][q] = 0.f;

    // ---- preload chunk 0 into buffer 0 ----
    {
        #pragma unroll
        for (int m4 = 0; m4 < 4; m4++) {
            uint4 v0 = *(const uint4*)(src[m4]);
            uint4 v1 = *(const uint4*)(src[m4] + 8);
            *(uint4*)(smem + m4 * MATB + stoff)      = v0;
            *(uint4*)(smem + m4 * MATB + stoff + 16) = v1;
        }
    }
    __syncthreads();

    const int nchunks = K / KCH;
    int cur = 0;
    for (int c = 0; c < nchunks; c++) {
        // prefetch next chunk GMEM -> regs
        uint4 v[8];
        const bool have_next = (c + 1 < nchunks);
        if (have_next) {
            const int k0 = (c + 1) * KCH;
            #pragma unroll
            for (int m4 = 0; m4 < 4; m4++) {
                v[m4 * 2]     = *(const uint4*)(src[m4] + k0);
                v[m4 * 2 + 1] = *(const uint4*)(src[m4] + k0 + 8);
            }
        }

        const uint32_t bufo = sb + (uint32_t)(cur * BUFB);
        #pragma unroll
        for (int ks = 0; ks < 2; ks++) {
            const uint32_t kb = ks * 32;
            uint32_t ahi[4][4], alo[4][4], bhi[4][2], blo[4][2];
            #pragma unroll
            for (int i = 0; i < 4; i++) {
                uint32_t ra = (uint32_t)(wm * 64 + i * 16) + arow;
                uint32_t ao = bufo + ra * ROWB + kb + akb;
                ldmx4(ao,        ahi[i][0], ahi[i][1], ahi[i][2], ahi[i][3]);
                ldmx4(ao + MATB, alo[i][0], alo[i][1], alo[i][2], alo[i][3]);
            }
            #pragma unroll
            for (int jj = 0; jj < 2; jj++) {
                uint32_t rb = (uint32_t)(wn * 32 + jj * 16) + brow;
                uint32_t bo = bufo + 2 * MATB + rb * ROWB + kb + bkb;
                uint32_t r0, r1, r2, r3;
                ldmx4(bo, r0, r1, r2, r3);
                bhi[jj*2][0] = r0; bhi[jj*2][1] = r1;
                bhi[jj*2+1][0] = r2; bhi[jj*2+1][1] = r3;
                ldmx4(bo + MATB, r0, r1, r2, r3);
                blo[jj*2][0] = r0; blo[jj*2][1] = r1;
                blo[jj*2+1][0] = r2; blo[jj*2+1][1] = r3;
            }
            #pragma unroll
            for (int i = 0; i < 4; i++)
                #pragma unroll
                for (int j = 0; j < 4; j++) {
                    mma16816(acc[i][j], ahi[i], bhi[j][0], bhi[j][1]);
                    mma16816(acc[i][j], ahi[i], blo[j][0], blo[j][1]);
                    mma16816(acc[i][j], alo[i], bhi[j][0], bhi[j][1]);
                }
        }

        if (have_next) {
            const int nb = cur ^ 1;
            #pragma unroll
            for (int m4 = 0; m4 < 4; m4++) {
                *(uint4*)(smem + nb * BUFB + m4 * MATB + stoff)      = v[m4 * 2];
                *(uint4*)(smem + nb * BUFB + m4 * MATB + stoff + 16) = v[m4 * 2 + 1];
            }
            __syncthreads();
            cur = nb;
        }
    }

    // epilogue: acc tile (i,j): rows bm+wm*64+i*16+{lane/4, +8}, cols bn+wn*32+j*8+(lane%4)*2
    const int er = lane >> 2;
    const int ec = (lane & 3) * 2;
    #pragma unroll
    for (int i = 0; i < 4; i++) {
        const int row0 = bm + wm * 64 + i * 16 + er;
        #pragma unroll
        for (int j = 0; j < 4; j++) {
            const int col = bn + wn * 32 + j * 8 + ec;
            *(float2*)&C[(size_t)row0 * N + col]       = make_float2(acc[i][j][0], acc[i][j][1]);
            *(float2*)&C[(size_t)(row0 + 8) * N + col] = make_float2(acc[i][j][2], acc[i][j][3]);
        }
    }
}

// ======================================================================
// RMSNorm + RoPE, warp-local: one warp per (t, head-slot).
// ======================================================================
__global__ __launch_bounds__(128) void norm_rope(
    const int* __restrict__ positions,
    const float* __restrict__ qw, const float* __restrict__ kw)
{
    const int slot = blockIdx.x * 4 + (threadIdx.x >> 5);
    const int lane = threadIdx.x & 31;
    const int t  = slot / (NH + NKV);
    const int hh = slot % (NH + NKV);
    const bool isq = hh < NH;

    const float* x = g_qkv + (size_t)t * QKVN +
                     (isq ? hh * HD : NH * HD + (hh - NH) * HD);

    float v0 = x[lane];
    float v1 = x[lane + 32];
    float v2 = x[lane + 64];
    float v3 = x[lane + 96];

    float ss = v0*v0 + v1*v1 + v2*v2 + v3*v3;
    #pragma unroll
    for (int o = 16; o; o >>= 1) ss += __shfl_xor_sync(0xffffffffu, ss, o);

    float rr = rsqrtf(ss * (1.0f / HD) + 1e-6f);
    const float* w = isq ? qw : kw;
    float x0 = v0 * rr * w[lane];
    float x1 = v1 * rr * w[lane + 32];
    float x2 = v2 * rr * w[lane + 64];
    float x3 = v3 * rr * w[lane + 96];

    const float pos = (float)positions[t];
    float f0 = 1.0f / powf(1000000.0f, (float)lane        * (1.0f / 64.0f));
    float f1 = 1.0f / powf(1000000.0f, (float)(lane + 32) * (1.0f / 64.0f));
    float s0, c0, s1, c1;
    sincosf(pos * f0, &s0, &c0);
    sincosf(pos * f1, &s1, &c1);

    float o0 = x0 * c0 - x2 * s0;
    float o1 = x1 * c1 - x3 * s1;
    float o2 = x2 * c0 + x0 * s0;
    float o3 = x3 * c1 + x1 * s1;

    float* dst = isq ? (g_q + (size_t)t * NH * HD + hh * HD)
                     : (g_k + (size_t)t * NKV * HD + (hh - NH) * HD);
    dst[lane]      = o0;
    dst[lane + 32] = o1;
    dst[lane + 64] = o2;
    dst[lane + 96] = o3;
}

// ======================================================================
// Causal GQA flash attention (fp32, online softmax) — unchanged.
// ======================================================================
__global__ __launch_bounds__(256) void attn_kernel(float* __restrict__ out)
{
    extern __shared__ float smem_att[];
    float (*Ks)[128] = (float(*)[128])smem_att;
    float (*Vs)[128] = (float(*)[128])(smem_att + 64 * 128);

    const int h     = blockIdx.y;
    const int qb    = (int)(gridDim.x - 1) - (int)blockIdx.x;
    const int kvh   = h >> 1;
    const int tid   = threadIdx.x;
    const int row   = tid >> 2;
    const int lane4 = tid & 3;
    const int lane  = tid & 31;
    const int qi    = qb * 64 + row;

    const float scale = 0.08838834764831845f;
    const float NEG   = -1e30f;

    float4 q4[8], o4[8];
    #pragma unroll
    for (int d4 = 0; d4 < 8; d4++) {
        float4 t = *(const float4*)(g_q + (size_t)qi * 2048 + h * 128 + (d4 * 4 + lane4) * 4);
        t.x *= scale; t.y *= scale; t.z *= scale; t.w *= scale;
        q4[d4] = t;
        o4[d4] = make_float4(0.f, 0.f, 0.f, 0.f);
    }
    float m = NEG, l = 0.f;

    for (int kt = 0; kt <= qb; kt++) {
        __syncthreads();
        #pragma unroll
        for (int u = tid; u < 64 * 32; u += 256) {
            int rr = u >> 5;
            int c4 = (u & 31) * 4;
            *(float4*)&Ks[rr][c4] =
                *(const float4*)(g_k + ((size_t)(kt * 64 + rr) * NKV + kvh) * 128 + c4);
            *(float4*)&Vs[rr][c4] =
                *(const float4*)(g_qkv + (size_t)(kt * 64 + rr) * QKVN + (NH + NKV) * HD + kvh * 128 + c4);
        }
        __syncthreads();

        float p[16];
        float mt = NEG;
        #pragma unroll
        for (int jj = 0; jj < 16; jj++) {
            float mine = 0.f;
            #pragma unroll
            for (int jofs = 0; jofs < 4; jofs++) {
                int j = jj * 4 + jofs;
                float part = 0.f;
                #pragma unroll
                for (int d4 = 0; d4 < 8; d4++) {
                    float4 kv = *(const float4*)&Ks[j][(d4 * 4 + lane4) * 4];
                    part += q4[d4].x * kv.x + q4[d4].y * kv.y
                          + q4[d4].z * kv.z + q4[d4].w * kv.w;
                }
                part += __shfl_xor_sync(0xffffffffu, part, 1);
                part += __shfl_xor_sync(0xffffffffu, part, 2);
                if (jofs == lane4) mine = part;
            }
            int kj = kt * 64 + jj * 4 + lane4;
            p[jj] = (kj <= qi) ? mine : NEG;
            mt = fmaxf(mt, p[jj]);
        }
        mt = fmaxf(mt, __shfl_xor_sync(0xffffffffu, mt, 1));
        mt = fmaxf(mt, __shfl_xor_sync(0xffffffffu, mt, 2));

        float mnew  = fmaxf(m, mt);
        float alpha = __expf(m - mnew);
        float lt = 0.f;
        #pragma unroll
        for (int jj = 0; jj < 16; jj++) {
            p[jj] = __expf(p[jj] - mnew);
            lt += p[jj];
        }
        lt += __shfl_xor_sync(0xffffffffu, lt, 1);
        lt += __shfl_xor_sync(0xffffffffu, lt, 2);
        l = l * alpha + lt;
        m = mnew;

        #pragma unroll
        for (int d4 = 0; d4 < 8; d4++) {
            o4[d4].x *= alpha; o4[d4].y *= alpha;
            o4[d4].z *= alpha; o4[d4].w *= alpha;
        }

        #pragma unroll
        for (int jj = 0; jj < 16; jj++) {
            #pragma unroll
            for (int jofs = 0; jofs < 4; jofs++) {
                float pj = __shfl_sync(0xffffffffu, p[jj], (lane & ~3) | jofs);
                int j = jj * 4 + jofs;
                #pragma unroll
                for (int d4 = 0; d4 < 8; d4++) {
                    float4 vv = *(const float4*)&Vs[j][(d4 * 4 + lane4) * 4];
                    o4[d4].x += pj * vv.x; o4[d4].y += pj * vv.y;
                    o4[d4].z += pj * vv.z; o4[d4].w += pj * vv.w;
                }
            }
        }
    }

    float invl = 1.f / l;
    #pragma unroll
    for (int d4 = 0; d4 < 8; d4++) {
        float4 t = o4[d4];
        t.x *= invl; t.y *= invl; t.z *= invl; t.w *= invl;
        *(float4*)(out + (size_t)qi * 2048 + h * 128 + (d4 * 4 + lane4) * 4) = t;
    }
}

// ======================================================================
// launch — inputs bound by element count (order-agnostic)
// ======================================================================
extern "C" void kernel_launch(void* const* d_in, const int* in_sizes, int n_in,
                              void* d_out, int out_size)
{
    const float* hidden    = 0;
    const int*   positions = 0;
    const float* qkv_w     = 0;
    const float* o_w       = 0;
    const float* qw        = 0;
    const float* kw        = 0;

    for (int i = 0; i < n_in; i++) {
        int s = in_sizes[i];
        if (s == QKVN * HID)            qkv_w = (const float*)d_in[i];
        else if (s == TT * HID) {
            if (!hidden) hidden = (const float*)d_in[i];
            else         o_w    = (const float*)d_in[i];
        }
        else if (s == TT)               positions = (const int*)d_in[i];
        else if (s == HD) {
            if (!qw) qw = (const float*)d_in[i];
            else     kw = (const float*)d_in[i];
        }
    }
    if (!kw) kw = qw;

    float* out = (float*)d_out;

    float *qkv_p, *att_p;
    cudaGetSymbolAddress((void**)&qkv_p, g_qkv);
    cudaGetSymbolAddress((void**)&att_p, g_att);
    __nv_bfloat16 *hid_hi, *hid_lo, *w1_hi, *w1_lo, *ow_hi, *ow_lo, *at_hi, *at_lo;
    cudaGetSymbolAddress((void**)&hid_hi, g_hid_hi);
    cudaGetSymbolAddress((void**)&hid_lo, g_hid_lo);
    cudaGetSymbolAddress((void**)&w1_hi,  g_w1_hi);
    cudaGetSymbolAddress((void**)&w1_lo,  g_w1_lo);
    cudaGetSymbolAddress((void**)&ow_hi,  g_ow_hi);
    cudaGetSymbolAddress((void**)&ow_lo,  g_ow_lo);
    cudaGetSymbolAddress((void**)&at_hi,  g_at_hi);
    cudaGetSymbolAddress((void**)&at_lo,  g_at_lo);

    cudaFuncSetAttribute(attn_kernel,
                         cudaFuncAttributeMaxDynamicSharedMemorySize, 65536);
    const int gemm_smem = 2 * BUFB;   // 81920
    cudaFuncSetAttribute(gemm_hmma,
                         cudaFuncAttributeMaxDynamicSharedMemorySize, gemm_smem);

    // 0. hi/lo splits of QKV-GEMM operands
    cvt_hilo<<<(TT * HID / 8 + 255) / 256, 256>>>(hidden, hid_hi, hid_lo, TT * HID / 8);
    cvt_hilo<<<(QKVN * HID / 8 + 255) / 256, 256>>>(qkv_w, w1_hi, w1_lo, QKVN * HID / 8);
    cvt_hilo<<<(HID * HID / 8 + 255) / 256, 256>>>(o_w, ow_hi, ow_lo, HID * HID / 8);

    // 1. QKV projection on tensor cores (HMMA)
    gemm_hmma<<<dim3(QKVN / 128, TT / 128), 256, gemm_smem>>>(
        hid_hi, hid_lo, w1_hi, w1_lo, qkv_p, QKVN, HID);

    // 2. RMSNorm + RoPE
    norm_rope<<<TT * (NH + NKV) / 4, 128>>>(positions, qw, kw);

    // 3. Causal GQA attention
    attn_kernel<<<dim3(TT / 64, NH), 256, 65536>>>(att_p);

    // 4. Output projection on tensor cores (HMMA)
    cvt_hilo<<<(TT * HID / 8 + 255) / 256, 256>>>(att_p, at_hi, at_lo, TT * HID / 8);
    gemm_hmma<<<dim3(HID / 128, TT / 128), 256, gemm_smem>>>(
        at_hi, at_lo, ow_hi, ow_lo, out, HID, HID);
}

// round 12
// speedup vs baseline: 2.9132x; 2.1048x over previous
#include <cuda_runtime.h>
#include <cuda_bf16.h>
#include <math.h>
#include <stdint.h>

#define TT   2048
#define HID  2048
#define NH   16
#define NKV  8
#define HD   128
#define QKVN 4096   /* NH*HD + 2*NKV*HD */

// ---------------- scratch (device globals: alloc-free rule) ----------------
__device__ float g_qkv[(size_t)TT * QKVN];      // 32 MB
__device__ float g_att[(size_t)TT * NH * HD];   // 16 MB  (attention output)

// bf16 hi/lo split copies for tensor-core GEMMs
__device__ __nv_bfloat16 g_hid_hi[(size_t)TT * HID];
__device__ __nv_bfloat16 g_hid_lo[(size_t)TT * HID];
__device__ __nv_bfloat16 g_w1_hi [(size_t)QKVN * HID];
__device__ __nv_bfloat16 g_w1_lo [(size_t)QKVN * HID];
__device__ __nv_bfloat16 g_ow_hi [(size_t)HID * HID];
__device__ __nv_bfloat16 g_ow_lo [(size_t)HID * HID];
__device__ __nv_bfloat16 g_at_hi [(size_t)TT * HID];
__device__ __nv_bfloat16 g_at_lo [(size_t)TT * HID];

// bf16 hi/lo Q/K/V for tensor-core attention
__device__ __nv_bfloat16 g_qh[(size_t)TT * NH * HD];
__device__ __nv_bfloat16 g_ql[(size_t)TT * NH * HD];
__device__ __nv_bfloat16 g_kh[(size_t)TT * NKV * HD];
__device__ __nv_bfloat16 g_kl[(size_t)TT * NKV * HD];
__device__ __nv_bfloat16 g_vh[(size_t)TT * NKV * HD];
__device__ __nv_bfloat16 g_vl[(size_t)TT * NKV * HD];

// ======================== helpers ========================
__device__ __forceinline__ uint32_t smem_u32(const void* p) {
    uint32_t a;
    asm("{ .reg .u64 t; cvta.to.shared.u64 t, %1; cvt.u32.u64 %0, t; }"
        : "=r"(a) : "l"(p));
    return a;
}
__device__ __forceinline__ void ldmx4(uint32_t addr, uint32_t& r0, uint32_t& r1,
                                      uint32_t& r2, uint32_t& r3) {
    asm volatile("ldmatrix.sync.aligned.m8n8.x4.shared.b16 {%0,%1,%2,%3}, [%4];"
                 : "=r"(r0), "=r"(r1), "=r"(r2), "=r"(r3) : "r"(addr));
}
__device__ __forceinline__ void ldmx4t(uint32_t addr, uint32_t& r0, uint32_t& r1,
                                       uint32_t& r2, uint32_t& r3) {
    asm volatile("ldmatrix.sync.aligned.m8n8.x4.trans.shared.b16 {%0,%1,%2,%3}, [%4];"
                 : "=r"(r0), "=r"(r1), "=r"(r2), "=r"(r3) : "r"(addr));
}
__device__ __forceinline__ void mma16816(float* c, const uint32_t* a,
                                         uint32_t b0, uint32_t b1) {
    asm volatile(
        "mma.sync.aligned.m16n8k16.row.col.f32.bf16.bf16.f32 "
        "{%0,%1,%2,%3}, {%4,%5,%6,%7}, {%8,%9}, {%0,%1,%2,%3};"
        : "+f"(c[0]), "+f"(c[1]), "+f"(c[2]), "+f"(c[3])
        : "r"(a[0]), "r"(a[1]), "r"(a[2]), "r"(a[3]), "r"(b0), "r"(b1));
}
__device__ __forceinline__ void cpa16(uint32_t dst, const void* src) {
    asm volatile("cp.async.cg.shared.global [%0], [%1], 16;"
                 :: "r"(dst), "l"(src) : "memory");
}
// pack two fp32 into bf16x2: low half = e0, high half = e1
__device__ __forceinline__ uint32_t packbf16(float e0, float e1) {
    uint32_t r;
    asm("cvt.rn.bf16x2.f32 %0, %1, %2;" : "=r"(r) : "f"(e1), "f"(e0));
    return r;
}
__device__ __forceinline__ void split2(float e0, float e1, uint32_t& hi, uint32_t& lo) {
    float h0 = __bfloat162float(__float2bfloat16(e0));
    float h1 = __bfloat162float(__float2bfloat16(e1));
    hi = packbf16(h0, h1);
    lo = packbf16(e0 - h0, e1 - h1);
}

// ======================================================================
// fp32 -> bf16 hi/lo split (8 floats per thread)
// ======================================================================
__global__ __launch_bounds__(256) void cvt_hilo(
    const float* __restrict__ x, __nv_bfloat16* __restrict__ hi,
    __nv_bfloat16* __restrict__ lo, int n8)
{
    int i = blockIdx.x * 256 + threadIdx.x;
    if (i >= n8) return;
    float4 a = ((const float4*)x)[i * 2];
    float4 b = ((const float4*)x)[i * 2 + 1];
    float v[8] = {a.x, a.y, a.z, a.w, b.x, b.y, b.z, b.w};
    __nv_bfloat16 h[8], l[8];
    #pragma unroll
    for (int k = 0; k < 8; k++) {
        h[k] = __float2bfloat16(v[k]);
        l[k] = __float2bfloat16(v[k] - __bfloat162float(h[k]));
    }
    *(uint4*)(hi + (size_t)i * 8) = *(uint4*)h;
    *(uint4*)(lo + (size_t)i * 8) = *(uint4*)l;
}

// V slice (strided inside qkv) -> contiguous bf16 hi/lo [T][NKV][HD]
__global__ __launch_bounds__(256) void cvt_v(
    const float* __restrict__ qkv,
    __nv_bfloat16* __restrict__ hi, __nv_bfloat16* __restrict__ lo)
{
    int i = blockIdx.x * 256 + threadIdx.x;      // float4 index
    const int n4 = TT * NKV * HD / 4;
    if (i >= n4) return;
    int idx = i * 4;
    int row = idx / HD;                          // t*NKV + kv
    int d   = idx % HD;
    int t = row / NKV, kv = row % NKV;
    float4 v = *(const float4*)(qkv + (size_t)t * QKVN + (NH + NKV) * HD + kv * HD + d);
    float e[4] = {v.x, v.y, v.z, v.w};
    __nv_bfloat16 h[4], l[4];
    #pragma unroll
    for (int k = 0; k < 4; k++) {
        h[k] = __float2bfloat16(e[k]);
        l[k] = __float2bfloat16(e[k] - __bfloat162float(h[k]));
    }
    *(uint2*)(hi + idx) = *(uint2*)h;
    *(uint2*)(lo + idx) = *(uint2*)l;
}

// ======================================================================
// HMMA bf16-split GEMM (unchanged — passing since round 7)
// ======================================================================
#define KCH    32
#define ROWB   80
#define MATB   (128 * ROWB)
#define BUFB   (4 * MATB)

__global__ __launch_bounds__(256, 1) void gemm_hmma(
    const __nv_bfloat16* __restrict__ Ahi, const __nv_bfloat16* __restrict__ Alo,
    const __nv_bfloat16* __restrict__ Bhi, const __nv_bfloat16* __restrict__ Blo,
    float* __restrict__ C, int N, int K)
{
    extern __shared__ char smem[];
    const uint32_t sb = smem_u32(smem);
    const int tid  = threadIdx.x;
    const int wid  = tid >> 5;
    const int lane = tid & 31;
    const int bm   = blockIdx.y * 128;
    const int bn   = blockIdx.x * 128;
    const int wm   = wid & 1;
    const int wn   = wid >> 1;

    const int r  = tid >> 1;
    const int ch = (tid & 1) * 16;
    const __nv_bfloat16* src[4] = {
        Ahi + (size_t)(bm + r) * K + ch,
        Alo + (size_t)(bm + r) * K + ch,
        Bhi + (size_t)(bn + r) * K + ch,
        Blo + (size_t)(bn + r) * K + ch };
    const uint32_t stoff = (uint32_t)(r * ROWB + ch * 2);

    const uint32_t arow = (uint32_t)((lane & 7) + ((lane & 8) ? 8 : 0));
    const uint32_t akb  = (lane & 16) ? 16u : 0u;
    const uint32_t brow = (uint32_t)((lane & 7) + ((lane & 16) ? 8 : 0));
    const uint32_t bkb  = (lane & 8) ? 16u : 0u;

    float acc[4][4][4];
    #pragma unroll
    for (int i = 0; i < 4; i++)
        #pragma unroll
        for (int j = 0; j < 4; j++)
            #pragma unroll
            for (int q = 0; q < 4; q++) acc[i][j][q] = 0.f;

    {
        #pragma unroll
        for (int m4 = 0; m4 < 4; m4++) {
            uint4 v0 = *(const uint4*)(src[m4]);
            uint4 v1 = *(const uint4*)(src[m4] + 8);
            *(uint4*)(smem + m4 * MATB + stoff)      = v0;
            *(uint4*)(smem + m4 * MATB + stoff + 16) = v1;
        }
    }
    __syncthreads();

    const int nchunks = K / KCH;
    int cur = 0;
    for (int c = 0; c < nchunks; c++) {
        uint4 v[8];
        const bool have_next = (c + 1 < nchunks);
        if (have_next) {
            const int k0 = (c + 1) * KCH;
            #pragma unroll
            for (int m4 = 0; m4 < 4; m4++) {
                v[m4 * 2]     = *(const uint4*)(src[m4] + k0);
                v[m4 * 2 + 1] = *(const uint4*)(src[m4] + k0 + 8);
            }
        }

        const uint32_t bufo = sb + (uint32_t)(cur * BUFB);
        #pragma unroll
        for (int ks = 0; ks < 2; ks++) {
            const uint32_t kb = ks * 32;
            uint32_t ahi[4][4], alo[4][4], bhi[4][2], blo[4][2];
            #pragma unroll
            for (int i = 0; i < 4; i++) {
                uint32_t ra = (uint32_t)(wm * 64 + i * 16) + arow;
                uint32_t ao = bufo + ra * ROWB + kb + akb;
                ldmx4(ao,        ahi[i][0], ahi[i][1], ahi[i][2], ahi[i][3]);
                ldmx4(ao + MATB, alo[i][0], alo[i][1], alo[i][2], alo[i][3]);
            }
            #pragma unroll
            for (int jj = 0; jj < 2; jj++) {
                uint32_t rb = (uint32_t)(wn * 32 + jj * 16) + brow;
                uint32_t bo = bufo + 2 * MATB + rb * ROWB + kb + bkb;
                uint32_t r0, r1, r2, r3;
                ldmx4(bo, r0, r1, r2, r3);
                bhi[jj*2][0] = r0; bhi[jj*2][1] = r1;
                bhi[jj*2+1][0] = r2; bhi[jj*2+1][1] = r3;
                ldmx4(bo + MATB, r0, r1, r2, r3);
                blo[jj*2][0] = r0; blo[jj*2][1] = r1;
                blo[jj*2+1][0] = r2; blo[jj*2+1][1] = r3;
            }
            #pragma unroll
            for (int i = 0; i < 4; i++)
                #pragma unroll
                for (int j = 0; j < 4; j++) {
                    mma16816(acc[i][j], ahi[i], bhi[j][0], bhi[j][1]);
                    mma16816(acc[i][j], ahi[i], blo[j][0], blo[j][1]);
                    mma16816(acc[i][j], alo[i], bhi[j][0], bhi[j][1]);
                }
        }

        if (have_next) {
            const int nb = cur ^ 1;
            #pragma unroll
            for (int m4 = 0; m4 < 4; m4++) {
                *(uint4*)(smem + nb * BUFB + m4 * MATB + stoff)      = v[m4 * 2];
                *(uint4*)(smem + nb * BUFB + m4 * MATB + stoff + 16) = v[m4 * 2 + 1];
            }
            __syncthreads();
            cur = nb;
        }
    }

    const int er = lane >> 2;
    const int ec = (lane & 3) * 2;
    #pragma unroll
    for (int i = 0; i < 4; i++) {
        const int row0 = bm + wm * 64 + i * 16 + er;
        #pragma unroll
        for (int j = 0; j < 4; j++) {
            const int col = bn + wn * 32 + j * 8 + ec;
            *(float2*)&C[(size_t)row0 * N + col]       = make_float2(acc[i][j][0], acc[i][j][1]);
            *(float2*)&C[(size_t)(row0 + 8) * N + col] = make_float2(acc[i][j][2], acc[i][j][3]);
        }
    }
}

// ======================================================================
// RMSNorm + RoPE -> bf16 hi/lo Q (pre-scaled) and K. One warp per slot.
// ======================================================================
__global__ __launch_bounds__(128) void norm_rope(
    const int* __restrict__ positions,
    const float* __restrict__ qw, const float* __restrict__ kw)
{
    const int slot = blockIdx.x * 4 + (threadIdx.x >> 5);
    const int lane = threadIdx.x & 31;
    const int t  = slot / (NH + NKV);
    const int hh = slot % (NH + NKV);
    const bool isq = hh < NH;

    const float* x = g_qkv + (size_t)t * QKVN +
                     (isq ? hh * HD : NH * HD + (hh - NH) * HD);

    float v0 = x[lane];
    float v1 = x[lane + 32];
    float v2 = x[lane + 64];
    float v3 = x[lane + 96];

    float ss = v0*v0 + v1*v1 + v2*v2 + v3*v3;
    #pragma unroll
    for (int o = 16; o; o >>= 1) ss += __shfl_xor_sync(0xffffffffu, ss, o);

    float rr = rsqrtf(ss * (1.0f / HD) + 1e-6f);
    const float* w = isq ? qw : kw;
    float x0 = v0 * rr * w[lane];
    float x1 = v1 * rr * w[lane + 32];
    float x2 = v2 * rr * w[lane + 64];
    float x3 = v3 * rr * w[lane + 96];

    const float pos = (float)positions[t];
    float f0 = 1.0f / powf(1000000.0f, (float)lane        * (1.0f / 64.0f));
    float f1 = 1.0f / powf(1000000.0f, (float)(lane + 32) * (1.0f / 64.0f));
    float s0, c0, s1, c1;
    sincosf(pos * f0, &s0, &c0);
    sincosf(pos * f1, &s1, &c1);

    const float sc = isq ? 0.08838834764831845f : 1.0f;   // fold softmax scale into Q
    float o0 = (x0 * c0 - x2 * s0) * sc;
    float o1 = (x1 * c1 - x3 * s1) * sc;
    float o2 = (x2 * c0 + x0 * s0) * sc;
    float o3 = (x3 * c1 + x1 * s1) * sc;

    size_t base = isq ? ((size_t)t * NH + hh) * HD
                      : ((size_t)t * NKV + (hh - NH)) * HD;
    __nv_bfloat16* dh = isq ? g_qh + base : g_kh + base;
    __nv_bfloat16* dl = isq ? g_ql + base : g_kl + base;

    float vv[4] = {o0, o1, o2, o3};
    int   dd[4] = {lane, lane + 32, lane + 64, lane + 96};
    #pragma unroll
    for (int k = 0; k < 4; k++) {
        __nv_bfloat16 h = __float2bfloat16(vv[k]);
        dh[dd[k]] = h;
        dl[dd[k]] = __float2bfloat16(vv[k] - __bfloat162float(h));
    }
}

// ======================================================================
// Tensor-core causal GQA flash attention.
// CTA: 64 q rows x 1 head, 4 warps (16 q rows each), KV blocks of 64.
// Scores: Qhi*Khi + Qhi*Klo + Qlo*Khi ; PV: Phi*Vhi + Phi*Vlo + Plo*Vhi.
// smem: Qh|Ql|Kh|Kl|Vh|Vl, each 64 rows x 272B (conflict-free ldmatrix).
// FIX (round 9): copy loops now transfer the FULL 128B half-row (u<8),
// previously u<4 left half of every row uninitialized -> NaN.
// ======================================================================
#define AMAT (64 * 272)

__global__ __launch_bounds__(128, 2) void attn_mma(
    const __nv_bfloat16* __restrict__ Qh, const __nv_bfloat16* __restrict__ Ql,
    const __nv_bfloat16* __restrict__ Kh, const __nv_bfloat16* __restrict__ Kl,
    const __nv_bfloat16* __restrict__ Vh, const __nv_bfloat16* __restrict__ Vl,
    float* __restrict__ out)
{
    extern __shared__ char sm[];
    const uint32_t s0  = smem_u32(sm);
    const uint32_t sQH = s0,            sQL = s0 + AMAT;
    const uint32_t sKH = s0 + 2 * AMAT, sKL = s0 + 3 * AMAT;
    const uint32_t sVH = s0 + 4 * AMAT, sVL = s0 + 5 * AMAT;

    const int h    = blockIdx.y;
    const int qb   = (int)gridDim.x - 1 - (int)blockIdx.x;  // heavy blocks first
    const int kvh  = h >> 1;
    const int tid  = threadIdx.x;
    const int wq   = tid >> 5;
    const int lane = tid & 31;

    const int cr  = tid >> 1;     // copy row 0..63
    const int chf = tid & 1;      // col half (64 elements = 128 bytes)

    // Q tile (hi/lo) -> smem, once: full 128B per (row, half)
    {
        size_t qoff = ((size_t)(qb * 64 + cr) * NH + h) * HD + chf * 64;
        uint32_t dh = sQH + cr * 272 + chf * 128;
        uint32_t dl = sQL + cr * 272 + chf * 128;
        #pragma unroll
        for (int u = 0; u < 8; u++) {
            cpa16(dh + u * 16, Qh + qoff + u * 8);
            cpa16(dl + u * 16, Ql + qoff + u * 8);
        }
    }
    asm volatile("cp.async.commit_group;");

    // per-lane ldmatrix offsets (bytes, within a 64x272B matrix)
    const uint32_t qoffm = (uint32_t)((wq * 16 + (lane & 15)) * 272 + ((lane & 16) ? 16 : 0));
    const uint32_t koffm = (uint32_t)((((lane & 7) + ((lane & 16) ? 8 : 0))) * 272 + ((lane & 8) ? 16 : 0));
    const uint32_t voffm = (uint32_t)((((lane & 7) + ((lane & 8) ? 8 : 0))) * 272 + ((lane & 16) ? 16 : 0));

    float O[16][4];
    #pragma unroll
    for (int i = 0; i < 16; i++)
        #pragma unroll
        for (int q = 0; q < 4; q++) O[i][q] = 0.f;
    float m0 = -1e30f, m1 = -1e30f, l0 = 0.f, l1 = 0.f;

    const int r0 = lane >> 2;
    const int c0 = (lane & 3) * 2;

    for (int kt = 0; kt <= qb; kt++) {
        __syncthreads();   // previous block's reads done
        {
            size_t base = ((size_t)(kt * 64 + cr) * NKV + kvh) * HD + chf * 64;
            uint32_t doff = cr * 272 + chf * 128;
            #pragma unroll
            for (int u = 0; u < 8; u++) {
                cpa16(sKH + doff + u * 16, Kh + base + u * 8);
                cpa16(sKL + doff + u * 16, Kl + base + u * 8);
                cpa16(sVH + doff + u * 16, Vh + base + u * 8);
                cpa16(sVL + doff + u * 16, Vl + base + u * 8);
            }
        }
        asm volatile("cp.async.commit_group;");
        asm volatile("cp.async.wait_group 0;");
        __syncthreads();

        // ---- scores S[64q x 64j] per warp: 16 x 64 ----
        float S[8][4];
        #pragma unroll
        for (int i = 0; i < 8; i++)
            #pragma unroll
            for (int q = 0; q < 4; q++) S[i][q] = 0.f;

        #pragma unroll
        for (int ks = 0; ks < 8; ks++) {
            uint32_t qh[4], ql[4];
            ldmx4(sQH + qoffm + ks * 32, qh[0], qh[1], qh[2], qh[3]);
            ldmx4(sQL + qoffm + ks * 32, ql[0], ql[1], ql[2], ql[3]);
            #pragma unroll
            for (int g = 0; g < 4; g++) {
                uint32_t ka = koffm + g * (16 * 272) + ks * 32;
                uint32_t kh0, kh1, kh2, kh3, kl0, kl1, kl2, kl3;
                ldmx4(sKH + ka, kh0, kh1, kh2, kh3);
                ldmx4(sKL + ka, kl0, kl1, kl2, kl3);
                mma16816(S[2*g],     qh, kh0, kh1);
                mma16816(S[2*g],     qh, kl0, kl1);
                mma16816(S[2*g],     ql, kh0, kh1);
                mma16816(S[2*g + 1], qh, kh2, kh3);
                mma16816(S[2*g + 1], qh, kl2, kl3);
                mma16816(S[2*g + 1], ql, kh2, kh3);
            }
        }

        // ---- causal mask (diagonal block only) ----
        if (kt == qb) {
            const int ra = wq * 16 + r0, rb = ra + 8;
            #pragma unroll
            for (int nt = 0; nt < 8; nt++) {
                int j = nt * 8 + c0;
                if (j     > ra) S[nt][0] = -1e30f;
                if (j + 1 > ra) S[nt][1] = -1e30f;
                if (j     > rb) S[nt][2] = -1e30f;
                if (j + 1 > rb) S[nt][3] = -1e30f;
            }
        }

        // ---- online softmax ----
        float mt0 = -1e30f, mt1 = -1e30f;
        #pragma unroll
        for (int nt = 0; nt < 8; nt++) {
            mt0 = fmaxf(mt0, fmaxf(S[nt][0], S[nt][1]));
            mt1 = fmaxf(mt1, fmaxf(S[nt][2], S[nt][3]));
        }
        mt0 = fmaxf(mt0, __shfl_xor_sync(0xffffffffu, mt0, 1));
        mt0 = fmaxf(mt0, __shfl_xor_sync(0xffffffffu, mt0, 2));
        mt1 = fmaxf(mt1, __shfl_xor_sync(0xffffffffu, mt1, 1));
        mt1 = fmaxf(mt1, __shfl_xor_sync(0xffffffffu, mt1, 2));

        float mn0 = fmaxf(m0, mt0), mn1 = fmaxf(m1, mt1);
        float al0 = __expf(m0 - mn0), al1 = __expf(m1 - mn1);
        m0 = mn0; m1 = mn1;

        float s0r = 0.f, s1r = 0.f;
        #pragma unroll
        for (int nt = 0; nt < 8; nt++) {
            S[nt][0] = __expf(S[nt][0] - mn0); s0r += S[nt][0];
            S[nt][1] = __expf(S[nt][1] - mn0); s0r += S[nt][1];
            S[nt][2] = __expf(S[nt][2] - mn1); s1r += S[nt][2];
            S[nt][3] = __expf(S[nt][3] - mn1); s1r += S[nt][3];
        }
        s0r += __shfl_xor_sync(0xffffffffu, s0r, 1);
        s0r += __shfl_xor_sync(0xffffffffu, s0r, 2);
        s1r += __shfl_xor_sync(0xffffffffu, s1r, 1);
        s1r += __shfl_xor_sync(0xffffffffu, s1r, 2);
        l0 = l0 * al0 + s0r;
        l1 = l1 * al1 + s1r;

        #pragma unroll
        for (int nd = 0; nd < 16; nd++) {
            O[nd][0] *= al0; O[nd][1] *= al0;
            O[nd][2] *= al1; O[nd][3] *= al1;
        }

        // ---- PV: O[16 x 128] += P[16 x 64] * V[64 x 128] ----
        #pragma unroll
        for (int g = 0; g < 4; g++) {
            uint32_t ph[4], pl[4];
            split2(S[2*g][0],     S[2*g][1],     ph[0], pl[0]);
            split2(S[2*g][2],     S[2*g][3],     ph[1], pl[1]);
            split2(S[2*g + 1][0], S[2*g + 1][1], ph[2], pl[2]);
            split2(S[2*g + 1][2], S[2*g + 1][3], ph[3], pl[3]);
            #pragma unroll
            for (int db = 0; db < 8; db++) {
                uint32_t va = voffm + g * (16 * 272) + db * 32;
                uint32_t vh0, vh1, vh2, vh3, vl0, vl1, vl2, vl3;
                ldmx4t(sVH + va, vh0, vh1, vh2, vh3);
                ldmx4t(sVL + va, vl0, vl1, vl2, vl3);
                mma16816(O[2*db],     ph, vh0, vh1);
                mma16816(O[2*db],     ph, vl0, vl1);
                mma16816(O[2*db],     pl, vh0, vh1);
                mma16816(O[2*db + 1], ph, vh2, vh3);
                mma16816(O[2*db + 1], ph, vl2, vl3);
                mma16816(O[2*db + 1], pl, vh2, vh3);
            }
        }
    }

    // ---- write out ----
    const float i0 = 1.f / l0, i1 = 1.f / l1;
    const int qg = qb * 64 + wq * 16;
    float* oa = out + (size_t)(qg + r0)     * (NH * HD) + h * HD + c0;
    float* ob = out + (size_t)(qg + r0 + 8) * (NH * HD) + h * HD + c0;
    #pragma unroll
    for (int nd = 0; nd < 16; nd++) {
        *(float2*)(oa + nd * 8) = make_float2(O[nd][0] * i0, O[nd][1] * i0);
        *(float2*)(ob + nd * 8) = make_float2(O[nd][2] * i1, O[nd][3] * i1);
    }
}

// ======================================================================
// launch — inputs bound by element count (order-agnostic)
// ======================================================================
extern "C" void kernel_launch(void* const* d_in, const int* in_sizes, int n_in,
                              void* d_out, int out_size)
{
    const float* hidden    = 0;
    const int*   positions = 0;
    const float* qkv_w     = 0;
    const float* o_w       = 0;
    const float* qw        = 0;
    const float* kw        = 0;

    for (int i = 0; i < n_in; i++) {
        int s = in_sizes[i];
        if (s == QKVN * HID)            qkv_w = (const float*)d_in[i];
        else if (s == TT * HID) {
            if (!hidden) hidden = (const float*)d_in[i];
            else         o_w    = (const float*)d_in[i];
        }
        else if (s == TT)               positions = (const int*)d_in[i];
        else if (s == HD) {
            if (!qw) qw = (const float*)d_in[i];
            else     kw = (const float*)d_in[i];
        }
    }
    if (!kw) kw = qw;

    float* out = (float*)d_out;

    float *qkv_p, *att_p;
    cudaGetSymbolAddress((void**)&qkv_p, g_qkv);
    cudaGetSymbolAddress((void**)&att_p, g_att);
    __nv_bfloat16 *hid_hi, *hid_lo, *w1_hi, *w1_lo, *ow_hi, *ow_lo, *at_hi, *at_lo;
    __nv_bfloat16 *qh, *ql, *kh, *kl, *vh, *vl;
    cudaGetSymbolAddress((void**)&hid_hi, g_hid_hi);
    cudaGetSymbolAddress((void**)&hid_lo, g_hid_lo);
    cudaGetSymbolAddress((void**)&w1_hi,  g_w1_hi);
    cudaGetSymbolAddress((void**)&w1_lo,  g_w1_lo);
    cudaGetSymbolAddress((void**)&ow_hi,  g_ow_hi);
    cudaGetSymbolAddress((void**)&ow_lo,  g_ow_lo);
    cudaGetSymbolAddress((void**)&at_hi,  g_at_hi);
    cudaGetSymbolAddress((void**)&at_lo,  g_at_lo);
    cudaGetSymbolAddress((void**)&qh, g_qh);
    cudaGetSymbolAddress((void**)&ql, g_ql);
    cudaGetSymbolAddress((void**)&kh, g_kh);
    cudaGetSymbolAddress((void**)&kl, g_kl);
    cudaGetSymbolAddress((void**)&vh, g_vh);
    cudaGetSymbolAddress((void**)&vl, g_vl);

    const int gemm_smem = 2 * BUFB;          // 81920
    cudaFuncSetAttribute(gemm_hmma,
                         cudaFuncAttributeMaxDynamicSharedMemorySize, gemm_smem);
    const int attn_smem = 6 * AMAT;          // 104448
    cudaFuncSetAttribute(attn_mma,
                         cudaFuncAttributeMaxDynamicSharedMemorySize, attn_smem);

    // 0. hi/lo splits of GEMM operands
    cvt_hilo<<<(TT * HID / 8 + 255) / 256, 256>>>(hidden, hid_hi, hid_lo, TT * HID / 8);
    cvt_hilo<<<(QKVN * HID / 8 + 255) / 256, 256>>>(qkv_w, w1_hi, w1_lo, QKVN * HID / 8);
    cvt_hilo<<<(HID * HID / 8 + 255) / 256, 256>>>(o_w, ow_hi, ow_lo, HID * HID / 8);

    // 1. QKV projection (HMMA)
    gemm_hmma<<<dim3(QKVN / 128, TT / 128), 256, gemm_smem>>>(
        hid_hi, hid_lo, w1_hi, w1_lo, qkv_p, QKVN, HID);

    // 2. RMSNorm + RoPE -> bf16 hi/lo Q,K ; V split
    norm_rope<<<TT * (NH + NKV) / 4, 128>>>(positions, qw, kw);
    cvt_v<<<(TT * NKV * HD / 4 + 255) / 256, 256>>>(qkv_p, vh, vl);

    // 3. Tensor-core causal attention
    attn_mma<<<dim3(TT / 64, NH), 128, attn_smem>>>(qh, ql, kh, kl, vh, vl, att_p);

    // 4. Output projection (HMMA)
    cvt_hilo<<<(TT * HID / 8 + 255) / 256, 256>>>(att_p, at_hi, at_lo, TT * HID / 8);
    gemm_hmma<<<dim3(HID / 128, TT / 128), 256, gemm_smem>>>(
        at_hi, at_lo, ow_hi, ow_lo, out, HID, HID);
}